// round 2
// baseline (speedup 1.0000x reference)
#include <cuda_runtime.h>

#define NNODES 50000
#define DD 16
#define BB 32
#define NDRVN 500
#define FEAT 5
#define NMID 5

// Ping-pong state buffers, node-major [N, B] — referenced directly by kernels,
// no cudaGetSymbolAddress needed.
__device__ float g_zA[NNODES * BB];
__device__ float g_zB[NNODES * BB];

// ---------------------------------------------------------------------------
// Transpose x [B, N] -> g_zA [N, B] (tiled through shared memory)
// ---------------------------------------------------------------------------
__global__ void transpose_kernel(const float* __restrict__ x) {
    __shared__ float tile[32][33];
    int n0 = blockIdx.x * 32;
    int tx = threadIdx.x, ty = threadIdx.y;
    int n = n0 + tx;
    if (n < NNODES) tile[ty][tx] = x[ty * NNODES + n];
    __syncthreads();
    int n2 = n0 + ty;
    if (n2 < NNODES) g_zA[n2 * BB + tx] = tile[tx][ty];
}

// ---------------------------------------------------------------------------
// One message pass: gather neighbors, 7-conv stack + relu, avgpool
// z layout: [N, B]; warp = node, lane = batch
// ---------------------------------------------------------------------------
template <int WIN>
__device__ __forceinline__ void mid_layer(float (&h)[FEAT][DD - 2],
                                          const float* __restrict__ sw,
                                          const float* __restrict__ sb) {
    #pragma unroll
    for (int w = 0; w < WIN - 2; w++) {
        float tmp[FEAT];
        #pragma unroll
        for (int co = 0; co < FEAT; co++) {
            float a = sb[co];
            #pragma unroll
            for (int ci = 0; ci < FEAT; ci++) {
                a = fmaf(sw[(co * FEAT + ci) * 3 + 0], h[ci][w + 0], a);
                a = fmaf(sw[(co * FEAT + ci) * 3 + 1], h[ci][w + 1], a);
                a = fmaf(sw[(co * FEAT + ci) * 3 + 2], h[ci][w + 2], a);
            }
            tmp[co] = fmaxf(a, 0.0f);
        }
        // in-place: h[*][w] no longer needed by later positions
        #pragma unroll
        for (int co = 0; co < FEAT; co++) h[co][w] = tmp[co];
    }
}

template <int SRC>   // SRC=0: read g_zA write g_zB;  SRC=1: read g_zB write g_zA
__global__ void __launch_bounds__(128)
pass_kernel(const int* __restrict__ nbr,
            const float* __restrict__ w_first, const float* __restrict__ b_first,
            const float* __restrict__ w_mid,   const float* __restrict__ b_mid,
            const float* __restrict__ w_last,  const float* __restrict__ b_last) {
    __shared__ float swf[FEAT * 3];
    __shared__ float sbf[FEAT];
    __shared__ float swm[NMID * FEAT * FEAT * 3];
    __shared__ float sbm[NMID * FEAT];
    __shared__ float swl[FEAT * 3];
    __shared__ float sbl[1];

    int t = threadIdx.x;
    if (t < FEAT * 3) swf[t] = w_first[t];
    if (t < FEAT) sbf[t] = b_first[t];
    for (int i = t; i < NMID * FEAT * FEAT * 3; i += blockDim.x) swm[i] = w_mid[i];
    if (t < NMID * FEAT) sbm[t] = b_mid[t];
    if (t < FEAT * 3) swl[t] = w_last[t];
    if (t == 0) sbl[0] = b_last[0];
    __syncthreads();

    const float* __restrict__ zin = SRC == 0 ? g_zA : g_zB;
    float* __restrict__ zout      = SRC == 0 ? g_zB : g_zA;

    unsigned gid = blockIdx.x * blockDim.x + threadIdx.x;
    if (gid >= (unsigned)NNODES * BB) return;
    int n = gid >> 5;   // node (warp-uniform)
    int b = gid & 31;   // batch = lane

    // Gather 16 neighbor states; idx load is warp-uniform, state load coalesced
    float v[DD];
    const int* nb = nbr + n * DD;
    #pragma unroll
    for (int d = 0; d < DD; d++) {
        int idx = __ldg(&nb[d]);
        v[d] = __ldg(&zin[idx * BB + b]);
    }

    // First conv: 1 -> 5 channels, width 16 -> 14
    float h[FEAT][DD - 2];
    #pragma unroll
    for (int c = 0; c < FEAT; c++) {
        #pragma unroll
        for (int w = 0; w < DD - 2; w++) {
            float a = sbf[c];
            a = fmaf(swf[c * 3 + 0], v[w + 0], a);
            a = fmaf(swf[c * 3 + 1], v[w + 1], a);
            a = fmaf(swf[c * 3 + 2], v[w + 2], a);
            h[c][w] = fmaxf(a, 0.0f);
        }
    }

    // 5 middle convs: 5 -> 5 channels, widths 14->12->10->8->6->4, in place
    mid_layer<14>(h, swm + 0 * FEAT * FEAT * 3, sbm + 0 * FEAT);
    mid_layer<12>(h, swm + 1 * FEAT * FEAT * 3, sbm + 1 * FEAT);
    mid_layer<10>(h, swm + 2 * FEAT * FEAT * 3, sbm + 2 * FEAT);
    mid_layer<8>(h,  swm + 3 * FEAT * FEAT * 3, sbm + 3 * FEAT);
    mid_layer<6>(h,  swm + 4 * FEAT * FEAT * 3, sbm + 4 * FEAT);

    // Last conv: 5 -> 1 channel, width 4 -> 2, then avgpool(2) -> 1
    float o[2];
    #pragma unroll
    for (int w = 0; w < 2; w++) {
        float a = sbl[0];
        #pragma unroll
        for (int ci = 0; ci < FEAT; ci++) {
            a = fmaf(swl[ci * 3 + 0], h[ci][w + 0], a);
            a = fmaf(swl[ci * 3 + 1], h[ci][w + 1], a);
            a = fmaf(swl[ci * 3 + 2], h[ci][w + 2], a);
        }
        o[w] = fmaxf(a, 0.0f);
    }
    zout[n * BB + b] = 0.5f * (o[0] + o[1]);
}

// ---------------------------------------------------------------------------
// Zero fill the output (it is poisoned before timing)
// ---------------------------------------------------------------------------
__global__ void zero_kernel(float4* __restrict__ out, int n4) {
    int i = blockIdx.x * blockDim.x + threadIdx.x;
    if (i < n4) out[i] = make_float4(0.f, 0.f, 0.f, 0.f);
}

// ---------------------------------------------------------------------------
// Masked softmax: only driver columns are nonzero.
// Z = sum_drivers exp(z-m) + (N-NDRV)*exp(-m),  m = max(0, max_drivers z)
// One block per batch element; final state is in g_zA after 4 passes.
// ---------------------------------------------------------------------------
__global__ void softmax_kernel(const int* __restrict__ drivers,
                               float* __restrict__ out) {
    __shared__ float red[512];
    int b = blockIdx.x;
    int t = threadIdx.x;

    float myv = 0.0f;
    int drv = -1;
    float mval = -INFINITY;
    if (t < NDRVN) {
        drv = drivers[t];
        myv = g_zA[drv * BB + b];
        mval = myv;
    }
    red[t] = mval;
    __syncthreads();
    #pragma unroll
    for (int s = 256; s > 0; s >>= 1) {
        if (t < s) red[t] = fmaxf(red[t], red[t + s]);
        __syncthreads();
    }
    float m = fmaxf(red[0], 0.0f);
    __syncthreads();

    float e = (t < NDRVN) ? expf(myv - m) : 0.0f;
    red[t] = e;
    __syncthreads();
    #pragma unroll
    for (int s = 256; s > 0; s >>= 1) {
        if (t < s) red[t] += red[t + s];
        __syncthreads();
    }
    float Z = red[0] + (float)(NNODES - NDRVN) * expf(-m);

    if (t < NDRVN) out[b * NNODES + drv] = e / Z;
}

// ---------------------------------------------------------------------------
extern "C" void kernel_launch(void* const* d_in, const int* in_sizes, int n_in,
                              void* d_out, int out_size) {
    const float* x       = (const float*)d_in[0];
    const int*   nbr     = (const int*)  d_in[1];
    const int*   drivers = (const int*)  d_in[2];
    // d_in[3] = driver_matrix (unused; drivers + one-hot structure suffice)
    const float* w_first = (const float*)d_in[4];
    const float* b_first = (const float*)d_in[5];
    const float* w_mid   = (const float*)d_in[6];
    const float* b_mid   = (const float*)d_in[7];
    const float* w_last  = (const float*)d_in[8];
    const float* b_last  = (const float*)d_in[9];
    float* out = (float*)d_out;

    // x [B,N] -> g_zA [N,B]
    transpose_kernel<<<(NNODES + 31) / 32, dim3(32, 32)>>>(x);

    const int total = NNODES * BB;          // 1,600,000
    const int blk = 128;
    const int grid = (total + blk - 1) / blk;

    // 4 passes: A->B->A->B->A  (final state in g_zA)
    pass_kernel<0><<<grid, blk>>>(nbr, w_first, b_first, w_mid, b_mid, w_last, b_last);
    pass_kernel<1><<<grid, blk>>>(nbr, w_first, b_first, w_mid, b_mid, w_last, b_last);
    pass_kernel<0><<<grid, blk>>>(nbr, w_first, b_first, w_mid, b_mid, w_last, b_last);
    pass_kernel<1><<<grid, blk>>>(nbr, w_first, b_first, w_mid, b_mid, w_last, b_last);

    // zero d_out, then scatter the 500 driver softmax values per batch
    int n4 = total / 4;
    zero_kernel<<<(n4 + 255) / 256, 256>>>((float4*)out, n4);
    softmax_kernel<<<BB, 512>>>(drivers, out);
}

// round 3
// speedup vs baseline: 1.0160x; 1.0160x over previous
#include <cuda_runtime.h>

#define NNODES 50000
#define DD 16
#define BB 32
#define NPAIR 16         // 2 batch elems per thread
#define NDRVN 500
#define FEAT 5
#define NMID 5

typedef unsigned long long u64;

// Ping-pong state buffers, node-major [N, B]
__device__ float g_zA[NNODES * BB];
__device__ float g_zB[NNODES * BB];

// ---------------------------------------------------------------------------
// Packed f32x2 helpers (FFMA2 is only reachable via PTX fma.rn.f32x2)
// ---------------------------------------------------------------------------
__device__ __forceinline__ u64 ffma2(u64 a, u64 b, u64 c) {
    u64 d;
    asm("fma.rn.f32x2 %0, %1, %2, %3;" : "=l"(d) : "l"(a), "l"(b), "l"(c));
    return d;
}
__device__ __forceinline__ u64 add2(u64 a, u64 b) {
    u64 d;
    asm("add.rn.f32x2 %0, %1, %2;" : "=l"(d) : "l"(a), "l"(b));
    return d;
}
__device__ __forceinline__ u64 relu2(u64 x) {
    unsigned lo, hi;
    asm("mov.b64 {%0,%1}, %2;" : "=r"(lo), "=r"(hi) : "l"(x));
    float a = fmaxf(__uint_as_float(lo), 0.0f);
    float b = fmaxf(__uint_as_float(hi), 0.0f);
    u64 r;
    asm("mov.b64 %0, {%1,%2};" : "=l"(r) : "r"(__float_as_uint(a)), "r"(__float_as_uint(b)));
    return r;
}
__device__ __forceinline__ u64 pack2(float w) {
    u64 r;
    unsigned u = __float_as_uint(w);
    asm("mov.b64 %0, {%1,%1};" : "=l"(r) : "r"(u));
    return r;
}

// ---------------------------------------------------------------------------
// Transpose x [B, N] -> g_zA [N, B]
// ---------------------------------------------------------------------------
__global__ void transpose_kernel(const float* __restrict__ x) {
    __shared__ float tile[32][33];
    int n0 = blockIdx.x * 32;
    int tx = threadIdx.x, ty = threadIdx.y;
    int n = n0 + tx;
    if (n < NNODES) tile[ty][tx] = x[ty * NNODES + n];
    __syncthreads();
    int n2 = n0 + ty;
    if (n2 < NNODES) g_zA[n2 * BB + tx] = tile[tx][ty];
}

// ---------------------------------------------------------------------------
// One message pass, batch-pair packed: thread = (node, batch-pair)
// ---------------------------------------------------------------------------
template <int WIN>
__device__ __forceinline__ void mid_layer(u64 (&h)[FEAT][DD - 2],
                                          const u64* __restrict__ sw,
                                          const u64* __restrict__ sb) {
    #pragma unroll
    for (int w = 0; w < WIN - 2; w++) {
        u64 tmp[FEAT];
        #pragma unroll
        for (int co = 0; co < FEAT; co++) {
            u64 a = sb[co];
            #pragma unroll
            for (int ci = 0; ci < FEAT; ci++) {
                a = ffma2(sw[(co * FEAT + ci) * 3 + 0], h[ci][w + 0], a);
                a = ffma2(sw[(co * FEAT + ci) * 3 + 1], h[ci][w + 1], a);
                a = ffma2(sw[(co * FEAT + ci) * 3 + 2], h[ci][w + 2], a);
            }
            tmp[co] = relu2(a);
        }
        #pragma unroll
        for (int co = 0; co < FEAT; co++) h[co][w] = tmp[co];
    }
}

template <int SRC>   // SRC=0: read g_zA write g_zB;  SRC=1: read g_zB write g_zA
__global__ void __launch_bounds__(128)
pass_kernel(const int* __restrict__ nbr,
            const float* __restrict__ w_first, const float* __restrict__ b_first,
            const float* __restrict__ w_mid,   const float* __restrict__ b_mid,
            const float* __restrict__ w_last,  const float* __restrict__ b_last) {
    __shared__ u64 swf[FEAT * 3];
    __shared__ u64 sbf[FEAT];
    __shared__ u64 swm[NMID * FEAT * FEAT * 3];
    __shared__ u64 sbm[NMID * FEAT];
    __shared__ u64 swl[FEAT * 3];
    __shared__ u64 sbl[1];

    int t = threadIdx.x;
    if (t < FEAT * 3) swf[t] = pack2(w_first[t]);
    if (t < FEAT) sbf[t] = pack2(b_first[t]);
    for (int i = t; i < NMID * FEAT * FEAT * 3; i += blockDim.x) swm[i] = pack2(w_mid[i]);
    if (t < NMID * FEAT) sbm[t] = pack2(b_mid[t]);
    if (t < FEAT * 3) swl[t] = pack2(w_last[t]);
    if (t == 0) sbl[0] = pack2(b_last[0]);
    __syncthreads();

    const u64* __restrict__ zin = SRC == 0 ? (const u64*)g_zA : (const u64*)g_zB;
    u64* __restrict__ zout      = SRC == 0 ? (u64*)g_zB : (u64*)g_zA;

    unsigned gid = blockIdx.x * blockDim.x + threadIdx.x;
    if (gid >= (unsigned)NNODES * NPAIR) return;
    int n = gid >> 4;   // node (uniform per half-warp)
    int p = gid & 15;   // batch pair

    // Gather 16 neighbor pair-states; 8B loads, coalesced per half-warp
    u64 v[DD];
    const int* nb = nbr + n * DD;
    #pragma unroll
    for (int d = 0; d < DD; d++) {
        int idx = __ldg(&nb[d]);
        v[d] = __ldg(&zin[idx * NPAIR + p]);
    }

    // First conv: 1 -> 5 channels, width 16 -> 14
    u64 h[FEAT][DD - 2];
    #pragma unroll
    for (int c = 0; c < FEAT; c++) {
        #pragma unroll
        for (int w = 0; w < DD - 2; w++) {
            u64 a = sbf[c];
            a = ffma2(swf[c * 3 + 0], v[w + 0], a);
            a = ffma2(swf[c * 3 + 1], v[w + 1], a);
            a = ffma2(swf[c * 3 + 2], v[w + 2], a);
            h[c][w] = relu2(a);
        }
    }

    // 5 middle convs: widths 14->12->10->8->6->4, in place
    mid_layer<14>(h, swm + 0 * FEAT * FEAT * 3, sbm + 0 * FEAT);
    mid_layer<12>(h, swm + 1 * FEAT * FEAT * 3, sbm + 1 * FEAT);
    mid_layer<10>(h, swm + 2 * FEAT * FEAT * 3, sbm + 2 * FEAT);
    mid_layer<8>(h,  swm + 3 * FEAT * FEAT * 3, sbm + 3 * FEAT);
    mid_layer<6>(h,  swm + 4 * FEAT * FEAT * 3, sbm + 4 * FEAT);

    // Last conv: 5 -> 1 channel, width 4 -> 2, relu, then avgpool(2)
    u64 o[2];
    #pragma unroll
    for (int w = 0; w < 2; w++) {
        u64 a = sbl[0];
        #pragma unroll
        for (int ci = 0; ci < FEAT; ci++) {
            a = ffma2(swl[ci * 3 + 0], h[ci][w + 0], a);
            a = ffma2(swl[ci * 3 + 1], h[ci][w + 1], a);
            a = ffma2(swl[ci * 3 + 2], h[ci][w + 2], a);
        }
        o[w] = relu2(a);
    }
    u64 s = add2(o[0], o[1]);
    u64 res = ffma2(s, pack2(0.5f), pack2(0.0f));
    zout[n * NPAIR + p] = res;
}

// ---------------------------------------------------------------------------
// Zero fill the output (poisoned before timing)
// ---------------------------------------------------------------------------
__global__ void zero_kernel(float4* __restrict__ out, int n4) {
    int i = blockIdx.x * blockDim.x + threadIdx.x;
    if (i < n4) out[i] = make_float4(0.f, 0.f, 0.f, 0.f);
}

// ---------------------------------------------------------------------------
// Masked softmax over driver columns only; final state in g_zA
// ---------------------------------------------------------------------------
__global__ void softmax_kernel(const int* __restrict__ drivers,
                               float* __restrict__ out) {
    __shared__ float red[512];
    int b = blockIdx.x;
    int t = threadIdx.x;

    float myv = 0.0f;
    int drv = -1;
    float mval = -INFINITY;
    if (t < NDRVN) {
        drv = drivers[t];
        myv = g_zA[drv * BB + b];
        mval = myv;
    }
    red[t] = mval;
    __syncthreads();
    #pragma unroll
    for (int s = 256; s > 0; s >>= 1) {
        if (t < s) red[t] = fmaxf(red[t], red[t + s]);
        __syncthreads();
    }
    float m = fmaxf(red[0], 0.0f);
    __syncthreads();

    float e = (t < NDRVN) ? expf(myv - m) : 0.0f;
    red[t] = e;
    __syncthreads();
    #pragma unroll
    for (int s = 256; s > 0; s >>= 1) {
        if (t < s) red[t] += red[t + s];
        __syncthreads();
    }
    float Z = red[0] + (float)(NNODES - NDRVN) * expf(-m);

    if (t < NDRVN) out[b * NNODES + drv] = e / Z;
}

// ---------------------------------------------------------------------------
extern "C" void kernel_launch(void* const* d_in, const int* in_sizes, int n_in,
                              void* d_out, int out_size) {
    const float* x       = (const float*)d_in[0];
    const int*   nbr     = (const int*)  d_in[1];
    const int*   drivers = (const int*)  d_in[2];
    // d_in[3] = driver_matrix (unused)
    const float* w_first = (const float*)d_in[4];
    const float* b_first = (const float*)d_in[5];
    const float* w_mid   = (const float*)d_in[6];
    const float* b_mid   = (const float*)d_in[7];
    const float* w_last  = (const float*)d_in[8];
    const float* b_last  = (const float*)d_in[9];
    float* out = (float*)d_out;

    transpose_kernel<<<(NNODES + 31) / 32, dim3(32, 32)>>>(x);

    const int total = NNODES * NPAIR;       // 800,000 threads
    const int blk = 128;
    const int grid = (total + blk - 1) / blk;

    pass_kernel<0><<<grid, blk>>>(nbr, w_first, b_first, w_mid, b_mid, w_last, b_last);
    pass_kernel<1><<<grid, blk>>>(nbr, w_first, b_first, w_mid, b_mid, w_last, b_last);
    pass_kernel<0><<<grid, blk>>>(nbr, w_first, b_first, w_mid, b_mid, w_last, b_last);
    pass_kernel<1><<<grid, blk>>>(nbr, w_first, b_first, w_mid, b_mid, w_last, b_last);

    int n4 = NNODES * BB / 4;
    zero_kernel<<<(n4 + 255) / 256, 256>>>((float4*)out, n4);
    softmax_kernel<<<BB, 512>>>(drivers, out);
}